// round 13
// baseline (speedup 1.0000x reference)
#include <cuda_runtime.h>

// Problem constants (fixed by reference_code)
#define H     20          // hidden units
#define G4    80          // 4*H gates
#define FIN   10          // input features
#define NB    32          // batches per CTA (= lanes)
#define NWARP 16          // warps 0-7: layer-1 group (A); warps 8-15: layer-2 group (B)
#define THREADS (NWARP*32)
#define CHUNK 4           // x timesteps staged per smem buffer

typedef unsigned long long u64;

// ---- packed f32x2 helpers (sm_100+; FFMA2 reachable only via PTX) ----
__device__ __forceinline__ u64 pk2(float lo, float hi) {
    u64 r; asm("mov.b64 %0, {%1,%2};" : "=l"(r) : "f"(lo), "f"(hi)); return r;
}
__device__ __forceinline__ void fma2(u64 &d, u64 a, u64 b) {
    asm("fma.rn.f32x2 %0, %1, %2, %0;" : "+l"(d) : "l"(a), "l"(b));
}
__device__ __forceinline__ float hadd2(u64 v) {
    float lo, hi; asm("mov.b64 {%0,%1}, %2;" : "=f"(lo), "=f"(hi) : "l"(v)); return lo + hi;
}

// sigmoid(x) = 1/(1+e^-x); tanh(x) = 2*sigmoid(2x)-1 (safe at |x| large: 1/inf -> 0)
__device__ __forceinline__ float sigf(float x) {
    float e = __expf(-x);
    return __fdividef(1.0f, 1.0f + e);
}
__device__ __forceinline__ float tanhfast(float x) {
    float e = __expf(-2.0f * x);
    float y = __fdividef(1.0f, 1.0f + e);
    return fmaf(2.0f, y, -1.0f);
}

// Compute 4 gate dot-products per unit (i,f,g,o), activate, update c, write h halves.
// z: operand pairs [2*NKP] (shared across units, zero-padded tail).
// sw: weight table [G4][2*NKP] u64, 16B-aligned rows (broadcast LDS.128 reads).
template<int NU, int NKP>
__device__ __forceinline__ void gates_update(
    int u0, int lane,
    const u64* __restrict__ z,
    const u64* __restrict__ sw,
    const float* __restrict__ bias,
    float* cst,
    u64* __restrict__ hp_out)      // [10*32] u64 (pair-major, lane-minor)
{
#pragma unroll
    for (int ui = 0; ui < NU; ui++) {
        const int u = u0 + ui;
        u64 ai = pk2(bias[u],      0.0f);
        u64 af = pk2(bias[u + 20], 0.0f);
        u64 ag = pk2(bias[u + 40], 0.0f);
        u64 ao = pk2(bias[u + 60], 0.0f);
        const ulonglong2* wi = (const ulonglong2*)(sw + (size_t)(u)      * (2*NKP));
        const ulonglong2* wf = (const ulonglong2*)(sw + (size_t)(u + 20) * (2*NKP));
        const ulonglong2* wg = (const ulonglong2*)(sw + (size_t)(u + 40) * (2*NKP));
        const ulonglong2* wo = (const ulonglong2*)(sw + (size_t)(u + 60) * (2*NKP));
#pragma unroll
        for (int j = 0; j < NKP; j++) {
            u64 z0 = z[2*j], z1 = z[2*j + 1];
            ulonglong2 a = wi[j], b = wf[j], c = wg[j], d = wo[j];
            fma2(ai, z0, a.x); fma2(ai, z1, a.y);
            fma2(af, z0, b.x); fma2(af, z1, b.y);
            fma2(ag, z0, c.x); fma2(ag, z1, c.y);
            fma2(ao, z0, d.x); fma2(ao, z1, d.y);
        }
        float iv = sigf(hadd2(ai));
        float fv = sigf(hadd2(af));
        float gv = tanhfast(hadd2(ag));
        float ov = sigf(hadd2(ao));
        float c  = fmaf(fv, cst[ui], iv * gv);
        cst[ui]  = c;
        float hv = ov * tanhfast(c);
        float* dst = (float*)(hp_out + ((u >> 1) * 32 + lane));
        dst[u & 1] = hv;
    }
}

__global__ void __launch_bounds__(THREADS, 1)
lstm2_pipelined_kernel(const float* __restrict__ x,
                       const float* __restrict__ w_ih0, const float* __restrict__ w_hh0,
                       const float* __restrict__ b_ih0, const float* __restrict__ b_hh0,
                       const float* __restrict__ w_ih1, const float* __restrict__ w_hh1,
                       const float* __restrict__ b_ih1, const float* __restrict__ b_hh1,
                       const float* __restrict__ w_fc,  const float* __restrict__ b_fc,
                       float* __restrict__ out, int T, int B)
{
    // layer-1 weights per gate: [x pairs 0..4 | h pairs 5..14 | pad 15]
    __shared__ __align__(16) u64 s_w1[G4 * 16];
    // layer-2 weights per gate: [h1 pairs 0..9 | h2 pairs 10..19]
    __shared__ __align__(16) u64 s_w2[G4 * 20];
    __shared__ float s_b0[G4], s_b1[G4];
    __shared__ __align__(16) u64 s_h1[2][10 * 32];   // double-buffered h1 pairs
    __shared__ __align__(16) u64 s_h2[2][10 * 32];   // double-buffered h2 pairs
    __shared__ __align__(16) u64 s_x[2][CHUNK][5 * 32];  // x pairs [buf][t'][k*32+lane]

    const int tid  = threadIdx.x;
    const int w    = tid >> 5;
    const int lane = tid & 31;
    const int b0   = blockIdx.x * NB;
    const int b    = b0 + lane;

    const u64* w_ih0_p = (const u64*)w_ih0;   // rows of 5 pairs
    const u64* w_hh0_p = (const u64*)w_hh0;   // rows of 10 pairs
    const u64* w_ih1_p = (const u64*)w_ih1;
    const u64* w_hh1_p = (const u64*)w_hh1;
    const u64* xg      = (const u64*)x;       // [B][T*5] pairs

    // ---- stage weights & biases ----
    for (int i = tid; i < G4 * 16; i += THREADS) {
        int g = i >> 4, k = i & 15;
        u64 v = 0;
        if (k < 5)       v = w_ih0_p[g * 5 + k];
        else if (k < 15) v = w_hh0_p[g * 10 + (k - 5)];
        s_w1[i] = v;
    }
    for (int i = tid; i < G4 * 20; i += THREADS) {
        int g = i / 20, k = i % 20;
        s_w2[i] = (k < 10) ? w_ih1_p[g * 10 + k] : w_hh1_p[g * 10 + (k - 10)];
    }
    for (int i = tid; i < G4; i += THREADS) {
        s_b0[i] = b_ih0[i] + b_hh0[i];
        s_b1[i] = b_ih1[i] + b_hh1[i];
    }
    // zero h buffers (both parities: 2*10*32 u64 contiguous)
    for (int i = tid; i < 2 * 10 * 32; i += THREADS) {
        s_h1[0][i] = 0ull;
        s_h2[0][i] = 0ull;
    }
    // preload x chunk 0 into buffer 0
    {
        const int TOT = NB * CHUNK * 5;
        for (int i = tid; i < TOT; i += THREADS) {
            int bl = i / (CHUNK * 5);
            int r  = i - bl * (CHUNK * 5);
            int tt = r / 5, k = r - tt * 5;
            int bb = b0 + bl;
            u64 v = 0;
            if (bb < B && tt < T) v = xg[(size_t)bb * (T * 5) + (size_t)tt * 5 + k];
            s_x[0][tt][k * 32 + bl] = v;
        }
    }
    __syncthreads();

    // group split: warps 0-7 -> layer 1 (A); warps 8-15 -> layer 2 (B).
    // Per SMSP (w&3): 2 A-warps + 2 B-warps.
    const bool isA = (w < 8);
    const int  gw  = w & 7;
    // unit assignment within group: warps 0-3 own 3 units, warps 4-7 own 2
    // (per SMSP: 3+2 = 5 units per group — balanced)
    const int u0 = (gw < 4) ? (3 * gw) : (12 + 2 * (gw - 4));

    float cst[3] = {0.f, 0.f, 0.f};

    // Pipelined iterations: at iteration t, group A computes h1(t) (t<T),
    // group B computes h2(t-1) (t>=1). ONE barrier per iteration.
#pragma unroll 1
    for (int t = 0; t <= T; t++) {
        const int rp = (t & 1) ^ 1;   // buffer holding h1(t-1) / parity helper
        const int wp = t & 1;

        // prefetch next x chunk into the other buffer (all threads help)
        if ((t & (CHUNK - 1)) == 0 && (t + CHUNK) < T) {
            const int tc = t + CHUNK;
            const int nb = (((t >> 2) & 1) ^ 1);
            const int TOT = NB * CHUNK * 5;
            for (int i = tid; i < TOT; i += THREADS) {
                int bl = i / (CHUNK * 5);
                int r  = i - bl * (CHUNK * 5);
                int tt = r / 5, k = r - tt * 5;
                int bb = b0 + bl;
                u64 v = 0;
                if (bb < B && (tc + tt) < T)
                    v = xg[(size_t)bb * (T * 5) + (size_t)(tc + tt) * 5 + k];
                s_x[nb][tt][k * 32 + bl] = v;
            }
        }

        if (isA) {
            // ---------- layer 1: h1(t) = f(x(t), h1(t-1)) ----------
            if (t < T) {
                u64 z[16];
                const int xb = (t >> 2) & 1;
#pragma unroll
                for (int k = 0; k < 5;  k++) z[k]     = s_x[xb][t & (CHUNK - 1)][k * 32 + lane];
#pragma unroll
                for (int k = 0; k < 10; k++) z[5 + k] = s_h1[rp][k * 32 + lane];
                z[15] = 0ull;
                if (gw < 4) gates_update<3, 8>(u0, lane, z, s_w1, s_b0, cst, s_h1[wp]);
                else        gates_update<2, 8>(u0, lane, z, s_w1, s_b0, cst, s_h1[wp]);
            }
        } else {
            // ---------- layer 2: h2(t-1) = f(h1(t-1), h2(t-2)) ----------
            if (t >= 1) {
                u64 z[20];
#pragma unroll
                for (int k = 0; k < 10; k++) z[k]      = s_h1[rp][k * 32 + lane]; // h1(t-1)
#pragma unroll
                for (int k = 0; k < 10; k++) z[10 + k] = s_h2[wp][k * 32 + lane]; // h2(t-2)
                if (gw < 4) gates_update<3, 10>(u0, lane, z, s_w2, s_b1, cst, s_h2[rp]);
                else        gates_update<2, 10>(u0, lane, z, s_w2, s_b1, cst, s_h2[rp]);
            }
        }
        __syncthreads();
    }

    // ---------- FC head: out[b] = h2(T-1) . w_fc + b_fc ----------
    if (w == 0 && b < B) {
        const u64* wf = (const u64*)w_fc;      // 10 pairs, broadcast
        u64 acc = 0ull;
#pragma unroll
        for (int k = 0; k < 10; k++)
            fma2(acc, s_h2[(T - 1) & 1][k * 32 + lane], wf[k]);
        out[b] = hadd2(acc) + b_fc[0];
    }
}

extern "C" void kernel_launch(void* const* d_in, const int* in_sizes, int n_in,
                              void* d_out, int out_size)
{
    const float* x     = (const float*)d_in[0];
    const float* w_ih0 = (const float*)d_in[1];
    const float* w_hh0 = (const float*)d_in[2];
    const float* b_ih0 = (const float*)d_in[3];
    const float* b_hh0 = (const float*)d_in[4];
    const float* w_ih1 = (const float*)d_in[5];
    const float* w_hh1 = (const float*)d_in[6];
    const float* b_ih1 = (const float*)d_in[7];
    const float* b_hh1 = (const float*)d_in[8];
    const float* w_fc  = (const float*)d_in[9];
    const float* b_fc  = (const float*)d_in[10];
    float* out = (float*)d_out;

    const int B = out_size;                    // output is [B, 1]
    const int T = in_sizes[0] / (B * FIN);     // x is [B, T, FIN]

    dim3 grid((B + NB - 1) / NB);
    dim3 block(THREADS);
    lstm2_pipelined_kernel<<<grid, block>>>(x, w_ih0, w_hh0, b_ih0, b_hh0,
                                            w_ih1, w_hh1, b_ih1, b_hh1,
                                            w_fc, b_fc, out, T, B);
}

// round 14
// speedup vs baseline: 1.0015x; 1.0015x over previous
#include <cuda_runtime.h>

// Problem constants (fixed by reference_code)
#define H     20          // hidden units
#define G4    80          // 4*H gates
#define FIN   10          // input features
#define NB    32          // batches per CTA (= lanes)
#define NWARP 16          // warps 0-7: layer-1 group (A); warps 8-15: layer-2 group (B)
#define THREADS (NWARP*32)
#define CHUNK 4           // x timesteps staged per smem buffer

typedef unsigned long long u64;

// ---- packed f32x2 helpers (sm_100+; FFMA2 reachable only via PTX) ----
__device__ __forceinline__ u64 pk2(float lo, float hi) {
    u64 r; asm("mov.b64 %0, {%1,%2};" : "=l"(r) : "f"(lo), "f"(hi)); return r;
}
__device__ __forceinline__ void fma2(u64 &d, u64 a, u64 b) {
    asm("fma.rn.f32x2 %0, %1, %2, %0;" : "+l"(d) : "l"(a), "l"(b));
}
__device__ __forceinline__ float hadd2(u64 v) {
    float lo, hi; asm("mov.b64 {%0,%1}, %2;" : "=f"(lo), "=f"(hi) : "l"(v)); return lo + hi;
}

// sigmoid(x) = 1/(1+e^-x); tanh(x) = 2*sigmoid(2x)-1 (safe at |x| large: 1/inf -> 0)
__device__ __forceinline__ float sigf(float x) {
    float e = __expf(-x);
    return __fdividef(1.0f, 1.0f + e);
}
__device__ __forceinline__ float tanhfast(float x) {
    float e = __expf(-2.0f * x);
    float y = __fdividef(1.0f, 1.0f + e);
    return fmaf(2.0f, y, -1.0f);
}

// Compute 4 gate dot-products per unit (i,f,g,o), activate, update c, write h halves.
// z: operand pairs [2*NKP] (shared across units, zero-padded tail).
// sw: weight table [G4][2*NKP] u64, 16B-aligned rows (broadcast LDS.128 reads).
template<int NU, int NKP>
__device__ __forceinline__ void gates_update(
    int u0, int lane,
    const u64* __restrict__ z,
    const u64* __restrict__ sw,
    const float* __restrict__ bias,
    float* cst,
    u64* __restrict__ hp_out)      // [10*32] u64 (pair-major, lane-minor)
{
#pragma unroll
    for (int ui = 0; ui < NU; ui++) {
        const int u = u0 + ui;
        u64 ai = pk2(bias[u],      0.0f);
        u64 af = pk2(bias[u + 20], 0.0f);
        u64 ag = pk2(bias[u + 40], 0.0f);
        u64 ao = pk2(bias[u + 60], 0.0f);
        const ulonglong2* wi = (const ulonglong2*)(sw + (size_t)(u)      * (2*NKP));
        const ulonglong2* wf = (const ulonglong2*)(sw + (size_t)(u + 20) * (2*NKP));
        const ulonglong2* wg = (const ulonglong2*)(sw + (size_t)(u + 40) * (2*NKP));
        const ulonglong2* wo = (const ulonglong2*)(sw + (size_t)(u + 60) * (2*NKP));
#pragma unroll
        for (int j = 0; j < NKP; j++) {
            u64 z0 = z[2*j], z1 = z[2*j + 1];
            ulonglong2 a = wi[j], b = wf[j], c = wg[j], d = wo[j];
            fma2(ai, z0, a.x); fma2(ai, z1, a.y);
            fma2(af, z0, b.x); fma2(af, z1, b.y);
            fma2(ag, z0, c.x); fma2(ag, z1, c.y);
            fma2(ao, z0, d.x); fma2(ao, z1, d.y);
        }
        float iv = sigf(hadd2(ai));
        float fv = sigf(hadd2(af));
        float gv = tanhfast(hadd2(ag));
        float ov = sigf(hadd2(ao));
        float c  = fmaf(fv, cst[ui], iv * gv);
        cst[ui]  = c;
        float hv = ov * tanhfast(c);
        float* dst = (float*)(hp_out + ((u >> 1) * 32 + lane));
        dst[u & 1] = hv;
    }
}

__global__ void __launch_bounds__(THREADS, 1)
lstm2_pipelined_kernel(const float* __restrict__ x,
                       const float* __restrict__ w_ih0, const float* __restrict__ w_hh0,
                       const float* __restrict__ b_ih0, const float* __restrict__ b_hh0,
                       const float* __restrict__ w_ih1, const float* __restrict__ w_hh1,
                       const float* __restrict__ b_ih1, const float* __restrict__ b_hh1,
                       const float* __restrict__ w_fc,  const float* __restrict__ b_fc,
                       float* __restrict__ out, int T, int B)
{
    // layer-1 weights per gate: [x pairs 0..4 | h pairs 5..14 | pad 15]
    __shared__ __align__(16) u64 s_w1[G4 * 16];
    // layer-2 weights per gate: [h1 pairs 0..9 | h2 pairs 10..19]
    __shared__ __align__(16) u64 s_w2[G4 * 20];
    __shared__ float s_b0[G4], s_b1[G4];
    __shared__ __align__(16) u64 s_h1[2][10 * 32];   // double-buffered h1 pairs
    __shared__ __align__(16) u64 s_h2[2][10 * 32];   // double-buffered h2 pairs
    __shared__ __align__(16) u64 s_x[2][CHUNK][5 * 32];  // x pairs [buf][t'][k*32+lane]

    const int tid  = threadIdx.x;
    const int w    = tid >> 5;
    const int lane = tid & 31;
    const int b0   = blockIdx.x * NB;
    const int b    = b0 + lane;

    const u64* w_ih0_p = (const u64*)w_ih0;   // rows of 5 pairs
    const u64* w_hh0_p = (const u64*)w_hh0;   // rows of 10 pairs
    const u64* w_ih1_p = (const u64*)w_ih1;
    const u64* w_hh1_p = (const u64*)w_hh1;
    const u64* xg      = (const u64*)x;       // [B][T*5] pairs

    // ---- stage weights & biases ----
    for (int i = tid; i < G4 * 16; i += THREADS) {
        int g = i >> 4, k = i & 15;
        u64 v = 0;
        if (k < 5)       v = w_ih0_p[g * 5 + k];
        else if (k < 15) v = w_hh0_p[g * 10 + (k - 5)];
        s_w1[i] = v;
    }
    for (int i = tid; i < G4 * 20; i += THREADS) {
        int g = i / 20, k = i % 20;
        s_w2[i] = (k < 10) ? w_ih1_p[g * 10 + k] : w_hh1_p[g * 10 + (k - 10)];
    }
    for (int i = tid; i < G4; i += THREADS) {
        s_b0[i] = b_ih0[i] + b_hh0[i];
        s_b1[i] = b_ih1[i] + b_hh1[i];
    }
    // zero h buffers (both parities: 2*10*32 u64 contiguous)
    for (int i = tid; i < 2 * 10 * 32; i += THREADS) {
        s_h1[0][i] = 0ull;
        s_h2[0][i] = 0ull;
    }
    // preload x chunk 0 into buffer 0
    {
        const int TOT = NB * CHUNK * 5;
        for (int i = tid; i < TOT; i += THREADS) {
            int bl = i / (CHUNK * 5);
            int r  = i - bl * (CHUNK * 5);
            int tt = r / 5, k = r - tt * 5;
            int bb = b0 + bl;
            u64 v = 0;
            if (bb < B && tt < T) v = xg[(size_t)bb * (T * 5) + (size_t)tt * 5 + k];
            s_x[0][tt][k * 32 + bl] = v;
        }
    }
    __syncthreads();

    // group split: warps 0-7 -> layer 1 (A); warps 8-15 -> layer 2 (B).
    // Per SMSP (w&3): 2 A-warps + 2 B-warps.
    const bool isA = (w < 8);
    const int  gw  = w & 7;
    // unit assignment within group: warps 0-3 own 3 units, warps 4-7 own 2
    // (per SMSP: 3+2 = 5 units per group — balanced)
    const int u0 = (gw < 4) ? (3 * gw) : (12 + 2 * (gw - 4));

    float cst[3] = {0.f, 0.f, 0.f};

    // Pipelined iterations: at iteration t, group A computes h1(t) (t<T),
    // group B computes h2(t-1) (t>=1). ONE barrier per iteration.
#pragma unroll 1
    for (int t = 0; t <= T; t++) {
        const int rp = (t & 1) ^ 1;   // buffer holding h1(t-1) / parity helper
        const int wp = t & 1;

        // prefetch next x chunk into the other buffer (all threads help)
        if ((t & (CHUNK - 1)) == 0 && (t + CHUNK) < T) {
            const int tc = t + CHUNK;
            const int nb = (((t >> 2) & 1) ^ 1);
            const int TOT = NB * CHUNK * 5;
            for (int i = tid; i < TOT; i += THREADS) {
                int bl = i / (CHUNK * 5);
                int r  = i - bl * (CHUNK * 5);
                int tt = r / 5, k = r - tt * 5;
                int bb = b0 + bl;
                u64 v = 0;
                if (bb < B && (tc + tt) < T)
                    v = xg[(size_t)bb * (T * 5) + (size_t)(tc + tt) * 5 + k];
                s_x[nb][tt][k * 32 + bl] = v;
            }
        }

        if (isA) {
            // ---------- layer 1: h1(t) = f(x(t), h1(t-1)) ----------
            if (t < T) {
                u64 z[16];
                const int xb = (t >> 2) & 1;
#pragma unroll
                for (int k = 0; k < 5;  k++) z[k]     = s_x[xb][t & (CHUNK - 1)][k * 32 + lane];
#pragma unroll
                for (int k = 0; k < 10; k++) z[5 + k] = s_h1[rp][k * 32 + lane];
                z[15] = 0ull;
                if (gw < 4) gates_update<3, 8>(u0, lane, z, s_w1, s_b0, cst, s_h1[wp]);
                else        gates_update<2, 8>(u0, lane, z, s_w1, s_b0, cst, s_h1[wp]);
            }
        } else {
            // ---------- layer 2: h2(t-1) = f(h1(t-1), h2(t-2)) ----------
            if (t >= 1) {
                u64 z[20];
#pragma unroll
                for (int k = 0; k < 10; k++) z[k]      = s_h1[rp][k * 32 + lane]; // h1(t-1)
#pragma unroll
                for (int k = 0; k < 10; k++) z[10 + k] = s_h2[wp][k * 32 + lane]; // h2(t-2)
                if (gw < 4) gates_update<3, 10>(u0, lane, z, s_w2, s_b1, cst, s_h2[rp]);
                else        gates_update<2, 10>(u0, lane, z, s_w2, s_b1, cst, s_h2[rp]);
            }
        }
        __syncthreads();
    }

    // ---------- FC head: out[b] = h2(T-1) . w_fc + b_fc ----------
    if (w == 0 && b < B) {
        const u64* wf = (const u64*)w_fc;      // 10 pairs, broadcast
        u64 acc = 0ull;
#pragma unroll
        for (int k = 0; k < 10; k++)
            fma2(acc, s_h2[(T - 1) & 1][k * 32 + lane], wf[k]);
        out[b] = hadd2(acc) + b_fc[0];
    }
}

extern "C" void kernel_launch(void* const* d_in, const int* in_sizes, int n_in,
                              void* d_out, int out_size)
{
    const float* x     = (const float*)d_in[0];
    const float* w_ih0 = (const float*)d_in[1];
    const float* w_hh0 = (const float*)d_in[2];
    const float* b_ih0 = (const float*)d_in[3];
    const float* b_hh0 = (const float*)d_in[4];
    const float* w_ih1 = (const float*)d_in[5];
    const float* w_hh1 = (const float*)d_in[6];
    const float* b_ih1 = (const float*)d_in[7];
    const float* b_hh1 = (const float*)d_in[8];
    const float* w_fc  = (const float*)d_in[9];
    const float* b_fc  = (const float*)d_in[10];
    float* out = (float*)d_out;

    const int B = out_size;                    // output is [B, 1]
    const int T = in_sizes[0] / (B * FIN);     // x is [B, T, FIN]

    dim3 grid((B + NB - 1) / NB);
    dim3 block(THREADS);
    lstm2_pipelined_kernel<<<grid, block>>>(x, w_ih0, w_hh0, b_ih0, b_hh0,
                                            w_ih1, w_hh1, b_ih1, b_hh1,
                                            w_fc, b_fc, out, T, B);
}